// round 9
// baseline (speedup 1.0000x reference)
#include <cuda_runtime.h>
#include <cuda_bf16.h>
#include <cstdint>

#define EPS 1e-5f
#define NB  512
#define NP  512
#define MT  (NB*NP)

// ---------------- device scratch ----------------
__device__ __nv_bfloat16 g_yhi[(size_t)MT * 256];
__device__ __nv_bfloat16 g_ylo[(size_t)MT * 256];
__device__ __nv_bfloat16 g_h2hi[(size_t)MT * 256];
__device__ __nv_bfloat16 g_h2lo[(size_t)MT * 256];
__device__ __nv_bfloat16 g_w2hi[256*128], g_w2lo[256*128];
__device__ __nv_bfloat16 g_w3hi[256*256], g_w3lo[256*256];
__device__ __nv_bfloat16 g_w4hi[128*256], g_w4lo[128*256];
__device__ float g_pooled[NB*256];
__device__ float g_pb[NB*256];
__device__ float g_sum1[128], g_ss1[128];
__device__ float g_sum2[256], g_ss2[256];
__device__ float g_cnt;
__device__ float g_scale1[128], g_shift1[128];
__device__ float g_scale2[256], g_shift2[256];

// ---------------- helpers ----------------
__device__ __forceinline__ uint32_t smem_u32(const void* p) {
    uint32_t a;
    asm("{ .reg .u64 t; cvta.to.shared.u64 t, %1; cvt.u32.u64 %0, t; }" : "=r"(a) : "l"(p));
    return a;
}
__device__ __forceinline__ void ldsm4(uint32_t* r, uint32_t addr) {
    asm volatile("ldmatrix.sync.aligned.m8n8.x4.shared.b16 {%0,%1,%2,%3}, [%4];"
        : "=r"(r[0]), "=r"(r[1]), "=r"(r[2]), "=r"(r[3]) : "r"(addr));
}
__device__ __forceinline__ void stsm4(uint32_t addr, uint32_t r0, uint32_t r1,
                                      uint32_t r2, uint32_t r3) {
    asm volatile("stmatrix.sync.aligned.m8n8.x4.shared.b16 [%0], {%1,%2,%3,%4};"
        :: "r"(addr), "r"(r0), "r"(r1), "r"(r2), "r"(r3) : "memory");
}
__device__ __forceinline__ void mma_bf16(float* c, const uint32_t* a, uint32_t b0, uint32_t b1) {
    asm volatile(
        "mma.sync.aligned.m16n8k16.row.col.f32.bf16.bf16.f32 "
        "{%0,%1,%2,%3},{%4,%5,%6,%7},{%8,%9},{%0,%1,%2,%3};\n"
        : "+f"(c[0]), "+f"(c[1]), "+f"(c[2]), "+f"(c[3])
        : "r"(a[0]), "r"(a[1]), "r"(a[2]), "r"(a[3]), "r"(b0), "r"(b1));
}
__device__ __forceinline__ uint32_t pk(float a, float b) {
    __nv_bfloat162 t;
    t.x = __float2bfloat16(a); t.y = __float2bfloat16(b);
    return *(uint32_t*)&t;
}
__device__ __forceinline__ float rnd(float v) {          // bf16 round-trip
    return __bfloat162float(__float2bfloat16(v));
}
__device__ __forceinline__ void cpa16(uint32_t dst, const void* src) {
    asm volatile("cp.async.cg.shared.global [%0], [%1], 16;" :: "r"(dst), "l"(src));
}
#define CPA_COMMIT() asm volatile("cp.async.commit_group;" ::: "memory")
#define CPA_WAIT0()  asm volatile("cp.async.wait_group 0;"  ::: "memory")
#define CPA_WAIT1()  asm volatile("cp.async.wait_group 1;"  ::: "memory")

// ---------------- fused prep ----------------
__global__ void k_prep(float* __restrict__ out, float* __restrict__ pooled,
                       const float* __restrict__ W2, const float* __restrict__ W3,
                       const float* __restrict__ W4) {
    int i = blockIdx.x * blockDim.x + threadIdx.x;
    if (i < 65536)  out[i] = 0.f;
    if (i < 131072) pooled[i] = 0.f;
    if (i < 128) { g_sum1[i] = 0.f; g_ss1[i] = 0.f; }
    if (i < 256) { g_sum2[i] = 0.f; g_ss2[i] = 0.f; }
    if (i == 0)  g_cnt = 0.f;
    if (i < 32768) {
        int k = i >> 8, n = i & 255;
        float v = W2[k * 256 + n];
        __nv_bfloat16 h = __float2bfloat16(v);
        g_w2hi[n * 128 + k] = h;
        g_w2lo[n * 128 + k] = __float2bfloat16(v - __bfloat162float(h));
    }
    if (i < 65536) {
        int k = i >> 8, n = i & 255;
        float v = W3[k * 256 + n];
        __nv_bfloat16 h = __float2bfloat16(v);
        g_w3hi[n * 256 + k] = h;
        g_w3lo[n * 256 + k] = __float2bfloat16(v - __bfloat162float(h));
    }
    if (i < 32768) {
        int k = i >> 7, n = i & 127;
        float v = W4[k * 128 + n];
        __nv_bfloat16 h = __float2bfloat16(v);
        g_w4hi[n * 256 + k] = h;
        g_w4lo[n * 256 + k] = __float2bfloat16(v - __bfloat162float(h));
    }
}

// masked stats over h = x@W1+b1 (h never stored)
__global__ void k_h_stats(const float* __restrict__ x, const int* __restrict__ mask,
                          const float* __restrict__ W1, const float* __restrict__ b1) {
    int c  = threadIdx.x;
    int p0 = blockIdx.x * 128;
    __shared__ float xs[128 * 6];
    __shared__ int   ms[128];
    for (int idx = c; idx < 768; idx += 128) xs[idx] = x[p0 * 6 + idx];
    ms[c] = mask[p0 + c];
    __syncthreads();
    float w0 = W1[0*128+c], w1 = W1[1*128+c], w2 = W1[2*128+c];
    float w3 = W1[3*128+c], w4 = W1[4*128+c], w5 = W1[5*128+c];
    float bb = b1[c];
    float s = 0.f, ss = 0.f; int cnt = 0;
    for (int i = 0; i < 128; i++) {
        if (!ms[i]) continue;
        const float* xp = &xs[i * 6];
        float t = bb + xp[0]*w0 + xp[1]*w1 + xp[2]*w2 + xp[3]*w3 + xp[4]*w4 + xp[5]*w5;
        s += t; ss += t * t; cnt++;
    }
    atomicAdd(&g_sum1[c], s);
    atomicAdd(&g_ss1[c],  ss);
    if (c == 0) atomicAdd(&g_cnt, (float)cnt);
}

__global__ void k_fin1(const float* __restrict__ g1, const float* __restrict__ be1) {
    int c = threadIdx.x;
    float cnt  = g_cnt;
    float mean = g_sum1[c] / cnt;
    float var  = g_ss1[c] / cnt - mean * mean;
    float sc   = g1[c] * rsqrtf(var + EPS);
    g_scale1[c] = sc; g_shift1[c] = be1[c] - mean * sc;
}
__global__ void k_fin2(const float* __restrict__ g2, const float* __restrict__ be2) {
    int c = threadIdx.x;
    float cnt  = g_cnt;
    float mean = g_sum2[c] / cnt;
    float var  = g_ss2[c] / cnt - mean * mean;
    float sc   = g2[c] * rsqrtf(var + EPS);
    g_scale2[c] = sc; g_shift2[c] = be2[c] - mean * sc;
}

__global__ void k_pb(const float* __restrict__ W3, const float* __restrict__ b3) {
    int b = blockIdx.x, j = threadIdx.x;
    __shared__ float pl[256];
    pl[j] = g_pooled[b * 256 + j];
    __syncthreads();
    float s = b3[j];
#pragma unroll 4
    for (int k = 0; k < 256; k++) s += pl[k] * W3[(256 + k) * 256 + j];
    g_pb[b * 256 + j] = s;
}

// ---------------- pipelined tensor GEMM, tile 128x128, BK=32, 256 thr, 2 CTA/SM
// AMODE: 0 = A pre-split bf16 hi/lo via cp.async (triple-buffered)
//        1 = A bf16 hi/lo LDG, reconstruct, bn+relu, re-split
//        2 = A computed from x@W1p+b1p (BN folded), relu, split
// EMODE: 0 = y: (+bias)*mask, stmatrix-store split bf16, fused max-pool
//        1 = h2: +bias[batch], stmatrix-store split bf16, fused masked stats
//        2 = out: (+bias)*mask, max over rows -> redT[batch*128+col]
#define ABUF  10240
#define PITCH 272          // epilogue tile row pitch (bytes)

template<int KTOT, int AMODE, int EMODE>
__global__ void __launch_bounds__(256, 2) k_tc(
    const float* __restrict__ xin,
    const __nv_bfloat16* __restrict__ Ahi, const __nv_bfloat16* __restrict__ Alo,
    const __nv_bfloat16* __restrict__ Bhi, const __nv_bfloat16* __restrict__ Blo,
    const float* __restrict__ bias, const int* __restrict__ maskp,
    const float* __restrict__ scA, const float* __restrict__ shA,
    const float* __restrict__ W1, const float* __restrict__ b1,
    __nv_bfloat16* __restrict__ Chi, __nv_bfloat16* __restrict__ Clo,
    float* __restrict__ redT)
{
    constexpr int C = KTOT / 32;
    constexpr int ADEPTH = (AMODE == 0) ? 3 : 2;
    constexpr int FBOFF  = (2 * ADEPTH + 4) * ABUF;

    extern __shared__ __align__(128) char sm[];
    const uint32_t sb = smem_u32(sm);
    float* fb     = (float*)(sm + FBOFF);
    float* bias_s = fb;                      // [128]
    float* redA   = fb + 128;                // [128]
    float* redB   = fb + 256;                // [128]
    int*   pool_s = (int*)redA;
    float* scs    = fb + 384;                // [256]
    float* shs    = scs + 256;               // [256]
    float* w1s    = shs + 256;               // [768]
    float* b1s    = w1s + 768;               // [128]

    const int tid  = threadIdx.x;
    const int wid  = tid >> 5;
    const int lane = tid & 31;
    const int warp_m = wid & 3;
    const int warp_n = wid >> 2;
    const int g  = lane >> 2, t4 = lane & 3;
    const int colBase = blockIdx.x * 128;
    const int rowBase = blockIdx.y * 128;
    const int batch   = rowBase >> 9;

    if (AMODE == 1) {
        for (int i = tid; i < KTOT; i += 256) { scs[i] = scA[i]; shs[i] = shA[i]; }
    }
    if (AMODE == 2) {
        for (int i = tid; i < 768; i += 256) w1s[i] = W1[i] * scA[i & 127];
        if (tid < 128) b1s[tid] = b1[tid] * scA[tid] + shA[tid];
    }
    if (tid < 128) bias_s[tid] = bias[(EMODE == 1 ? batch * 256 : 0) + colBase + tid];
    __syncthreads();

    float xr[2][6];
    if (AMODE == 2) {
#pragma unroll
        for (int i = 0; i < 2; i++) {
            int row = (tid + i * 256) >> 2;
            const float* xp = xin + (size_t)(rowBase + row) * 6;
            float2 a = *(const float2*)xp;
            float2 b = *(const float2*)(xp + 2);
            float2 cc = *(const float2*)(xp + 4);
            xr[i][0] = a.x; xr[i][1] = a.y; xr[i][2] = b.x;
            xr[i][3] = b.y; xr[i][4] = cc.x; xr[i][5] = cc.y;
        }
    }

    float acc[2][8][4];
#pragma unroll
    for (int i = 0; i < 2; i++)
#pragma unroll
        for (int j = 0; j < 8; j++)
#pragma unroll
            for (int l = 0; l < 4; l++) acc[i][j][l] = 0.f;

    const int lrow = lane & 7, lsel = lane >> 3;
    const int aRowOff = (lsel & 1) * 8 + lrow, aKOff = (lsel >> 1) * 8;
    const int bRowOff = (lsel >> 1) * 8 + lrow, bKOff = (lsel & 1) * 8;

    auto stageA_async = [&](int k0, int buf) {
#pragma unroll
        for (int i = 0; i < 2; i++) {
            int idx = tid + i * 256;
            int row = idx >> 2, k8 = (idx & 3) * 8;
            uint32_t so = (uint32_t)(row * 40 + k8) * 2;
            size_t go = (size_t)(rowBase + row) * KTOT + k0 + k8;
            cpa16(sb + buf * ABUF + so,            Ahi + go);
            cpa16(sb + (ADEPTH + buf) * ABUF + so, Alo + go);
        }
    };
    auto stageA_compute = [&](int k0, int buf) {
#pragma unroll
        for (int i = 0; i < 2; i++) {
            int idx = tid + i * 256;
            int row = idx >> 2, k8 = (idx & 3) * 8;
            int kb = k0 + k8;
            float4 a0 = *(const float4*)&b1s[kb];
            float4 a1 = *(const float4*)&b1s[kb + 4];
#pragma unroll
            for (int d = 0; d < 6; d++) {
                float xv = xr[i][d];
                float4 w0 = *(const float4*)&w1s[d * 128 + kb];
                float4 w1v = *(const float4*)&w1s[d * 128 + kb + 4];
                a0.x += xv * w0.x;  a0.y += xv * w0.y;
                a0.z += xv * w0.z;  a0.w += xv * w0.w;
                a1.x += xv * w1v.x; a1.y += xv * w1v.y;
                a1.z += xv * w1v.z; a1.w += xv * w1v.w;
            }
            float tv[8] = {fmaxf(a0.x,0.f), fmaxf(a0.y,0.f), fmaxf(a0.z,0.f), fmaxf(a0.w,0.f),
                           fmaxf(a1.x,0.f), fmaxf(a1.y,0.f), fmaxf(a1.z,0.f), fmaxf(a1.w,0.f)};
            uint32_t H[4], L[4];
#pragma unroll
            for (int jp = 0; jp < 4; jp++) {
                float h0 = rnd(tv[jp*2]), h1 = rnd(tv[jp*2+1]);
                H[jp] = pk(tv[jp*2], tv[jp*2+1]);
                L[jp] = pk(tv[jp*2] - h0, tv[jp*2+1] - h1);
            }
            uint32_t so = (uint32_t)(row * 40 + k8) * 2;
            *(uint4*)(sm + buf * ABUF + so)            = make_uint4(H[0], H[1], H[2], H[3]);
            *(uint4*)(sm + (ADEPTH + buf) * ABUF + so) = make_uint4(L[0], L[1], L[2], L[3]);
        }
    };
    auto stageB = [&](int k0, int buf) {
#pragma unroll
        for (int i = 0; i < 2; i++) {
            int idx = tid + i * 256;
            int row = idx >> 2, k8 = (idx & 3) * 8;
            uint32_t so = (uint32_t)(row * 40 + k8) * 2;
            size_t go = (size_t)(colBase + row) * KTOT + k0 + k8;
            cpa16(sb + (2 * ADEPTH + buf) * ABUF + so,     Bhi + go);
            cpa16(sb + (2 * ADEPTH + 2 + buf) * ABUF + so, Blo + go);
        }
    };

    // AMODE==1: A = hi/lo bf16 -> reconstruct fp32 in regs
    float pf[AMODE == 1 ? 16 : 1];
    const int ldRow1 = tid >> 1, ldKh1 = (tid & 1) * 16;
    auto ldgA1 = [&](int k0) {
        size_t go = (size_t)(rowBase + ldRow1) * KTOT + k0 + ldKh1;
        uint4 H0 = *(const uint4*)(Ahi + go);
        uint4 H1 = *(const uint4*)(Ahi + go + 8);
        uint4 L0 = *(const uint4*)(Alo + go);
        uint4 L1 = *(const uint4*)(Alo + go + 8);
        const uint32_t hw[8] = {H0.x,H0.y,H0.z,H0.w,H1.x,H1.y,H1.z,H1.w};
        const uint32_t lw[8] = {L0.x,L0.y,L0.z,L0.w,L1.x,L1.y,L1.z,L1.w};
#pragma unroll
        for (int q = 0; q < 8; q++) {
            __nv_bfloat162 h = *(const __nv_bfloat162*)&hw[q];
            __nv_bfloat162 l = *(const __nv_bfloat162*)&lw[q];
            pf[q*2]   = __bfloat162float(h.x) + __bfloat162float(l.x);
            pf[q*2+1] = __bfloat162float(h.y) + __bfloat162float(l.y);
        }
    };
    auto stsA1 = [&](int k0, int buf) {
        int kb = k0 + ldKh1;
        uint32_t H[8], L[8];
#pragma unroll
        for (int q = 0; q < 4; q++) {
            float4 sc4 = *(const float4*)&scs[kb + q * 4];
            float4 sh4 = *(const float4*)&shs[kb + q * 4];
            float t0 = fmaxf(pf[q*4+0] * sc4.x + sh4.x, 0.f);
            float t1 = fmaxf(pf[q*4+1] * sc4.y + sh4.y, 0.f);
            float t2 = fmaxf(pf[q*4+2] * sc4.z + sh4.z, 0.f);
            float t3 = fmaxf(pf[q*4+3] * sc4.w + sh4.w, 0.f);
            H[q*2]   = pk(t0, t1); H[q*2+1] = pk(t2, t3);
            L[q*2]   = pk(t0 - rnd(t0), t1 - rnd(t1));
            L[q*2+1] = pk(t2 - rnd(t2), t3 - rnd(t3));
        }
        uint32_t so = (uint32_t)(ldRow1 * 40 + ldKh1) * 2;
        *(uint4*)(sm + buf * ABUF + so)                 = make_uint4(H[0], H[1], H[2], H[3]);
        *(uint4*)(sm + buf * ABUF + so + 16)            = make_uint4(H[4], H[5], H[6], H[7]);
        *(uint4*)(sm + (ADEPTH + buf) * ABUF + so)      = make_uint4(L[0], L[1], L[2], L[3]);
        *(uint4*)(sm + (ADEPTH + buf) * ABUF + so + 16) = make_uint4(L[4], L[5], L[6], L[7]);
    };

    auto mma_chunk = [&](int abuf, int bbuf) {
#pragma unroll
        for (int kk = 0; kk < 32; kk += 16) {
            uint32_t ah[2][4], al[2][4];
#pragma unroll
            for (int mt = 0; mt < 2; mt++) {
                int ar = warp_m * 32 + mt * 16;
                uint32_t off = (uint32_t)((ar + aRowOff) * 40 + kk + aKOff) * 2;
                ldsm4(ah[mt], sb + abuf * ABUF + off);
                ldsm4(al[mt], sb + (ADEPTH + abuf) * ABUF + off);
            }
#pragma unroll
            for (int ng = 0; ng < 4; ng++) {
                int bn = warp_n * 64 + ng * 16;
                uint32_t off = (uint32_t)((bn + bRowOff) * 40 + kk + bKOff) * 2;
                uint32_t bh[4], bl[4];
                ldsm4(bh, sb + (2 * ADEPTH + bbuf) * ABUF + off);
                ldsm4(bl, sb + (2 * ADEPTH + 2 + bbuf) * ABUF + off);
#pragma unroll
                for (int hf = 0; hf < 2; hf++) {
                    int nt = ng * 2 + hf;
                    uint32_t b0 = bh[hf * 2], b1r = bh[hf * 2 + 1];
                    uint32_t c0 = bl[hf * 2], c1r = bl[hf * 2 + 1];
#pragma unroll
                    for (int mt = 0; mt < 2; mt++) {
                        mma_bf16(acc[mt][nt], ah[mt], b0, b1r);
                        mma_bf16(acc[mt][nt], ah[mt], c0, c1r);
                        mma_bf16(acc[mt][nt], al[mt], b0, b1r);
                    }
                }
            }
        }
    };

    if (AMODE == 0) {
        stageA_async(0, 0); stageB(0, 0); CPA_COMMIT();
        stageA_async(32, 1); CPA_COMMIT();
        CPA_WAIT1(); __syncthreads();
        for (int c = 0; c < C; c++) {
            if (c + 1 < C) stageB((c + 1) * 32, (c + 1) & 1);
            CPA_COMMIT();
            if (c + 2 < C) stageA_async((c + 2) * 32, (c + 2) % 3);
            CPA_COMMIT();
            mma_chunk(c % 3, c & 1);
            CPA_WAIT1(); __syncthreads();
        }
    } else {
        if (AMODE == 2) stageA_compute(0, 0);
        else          { ldgA1(0); stsA1(0, 0); }
        stageB(0, 0);
        CPA_COMMIT();
        CPA_WAIT0();
        __syncthreads();
        for (int c = 0; c < C; c++) {
            const int buf = c & 1;
            if (c + 1 < C) {
                const int k0n = (c + 1) * 32;
                if (AMODE == 2) stageA_compute(k0n, buf ^ 1);
                else            ldgA1(k0n);
                stageB(k0n, buf ^ 1);
                CPA_COMMIT();
            }
            mma_chunk(buf, buf);
            if (AMODE == 1 && c + 1 < C) stsA1((c + 1) * 32, buf ^ 1);
            CPA_WAIT0();
            __syncthreads();
        }
    }

    // ---------------- epilogue ----------------
    // mask per (mt, rowhalf)
    float mrow[2][2];
    if (EMODE != 1) {
#pragma unroll
        for (int mt = 0; mt < 2; mt++) {
            mrow[mt][0] = (maskp[rowBase + warp_m*32 + mt*16 + g]     != 0) ? 1.f : 0.f;
            mrow[mt][1] = (maskp[rowBase + warp_m*32 + mt*16 + g + 8] != 0) ? 1.f : 0.f;
        }
    } else {
#pragma unroll
        for (int mt = 0; mt < 2; mt++) {
            mrow[mt][0] = (maskp[rowBase + warp_m*32 + mt*16 + g]     != 0) ? 1.f : 0.f;
            mrow[mt][1] = (maskp[rowBase + warp_m*32 + mt*16 + g + 8] != 0) ? 1.f : 0.f;
        }
    }

    if (tid < 128) { pool_s[tid] = 0; redA[tid] = 0.f; redB[tid] = 0.f; }
    __syncthreads();

    // stmatrix lane addressing
    const int smrow = lane & 7, ssel = lane >> 3;
    auto tile_addr = [&](int mt, int ntp) {
        return sb + (uint32_t)(warp_m*32 + mt*16 + (ssel & 1)*8 + smrow) * PITCH
                  + (uint32_t)(warp_n*64 + ntp*16 + (ssel >> 1)*8) * 2;
    };
    auto copy_out = [&](__nv_bfloat16* dst) {
        int seg = tid & 15;
#pragma unroll
        for (int it = 0; it < 8; it++) {
            int row = it * 16 + (tid >> 4);
            uint4 v = *(uint4*)(sm + row * PITCH + seg * 16);
            *(uint4*)(dst + (size_t)(rowBase + row) * 256 + colBase + seg * 8) = v;
        }
    };

    if (EMODE == 0 || EMODE == 1) {
        // ---- pass 1: hi tile (+ pool or stats) ----
#pragma unroll
        for (int mt = 0; mt < 2; mt++) {
#pragma unroll
            for (int ntp = 0; ntp < 4; ntp++) {
                int ntA = ntp * 2, ntB = ntA + 1;
                int lcA = warp_n*64 + ntA*8 + 2*t4;
                int lcB = warp_n*64 + ntB*8 + 2*t4;
                float bAx = bias_s[lcA], bAy = bias_s[lcA+1];
                float bBx = bias_s[lcB], bBy = bias_s[lcB+1];
                float a00 = acc[mt][ntA][0]+bAx, a01 = acc[mt][ntA][1]+bAy;
                float a10 = acc[mt][ntA][2]+bAx, a11 = acc[mt][ntA][3]+bAy;
                float b00 = acc[mt][ntB][0]+bBx, b01 = acc[mt][ntB][1]+bBy;
                float b10 = acc[mt][ntB][2]+bBx, b11 = acc[mt][ntB][3]+bBy;
                if (EMODE == 0) {
                    a00 *= mrow[mt][0]; a01 *= mrow[mt][0];
                    a10 *= mrow[mt][1]; a11 *= mrow[mt][1];
                    b00 *= mrow[mt][0]; b01 *= mrow[mt][0];
                    b10 *= mrow[mt][1]; b11 *= mrow[mt][1];
                    float pA0 = fmaxf(a00,a10), pA1 = fmaxf(a01,a11);
                    float pB0 = fmaxf(b00,b10), pB1 = fmaxf(b01,b11);
                    if (pA0 > 0.f) atomicMax(&pool_s[lcA],   __float_as_int(pA0));
                    if (pA1 > 0.f) atomicMax(&pool_s[lcA+1], __float_as_int(pA1));
                    if (pB0 > 0.f) atomicMax(&pool_s[lcB],   __float_as_int(pB0));
                    if (pB1 > 0.f) atomicMax(&pool_s[lcB+1], __float_as_int(pB1));
                } else {
                    // stats from reconstructed (hi+lo) values
                    float ra00 = rnd(a00) + rnd(a00 - rnd(a00));
                    float ra01 = rnd(a01) + rnd(a01 - rnd(a01));
                    float ra10 = rnd(a10) + rnd(a10 - rnd(a10));
                    float ra11 = rnd(a11) + rnd(a11 - rnd(a11));
                    float rb00 = rnd(b00) + rnd(b00 - rnd(b00));
                    float rb01 = rnd(b01) + rnd(b01 - rnd(b01));
                    float rb10 = rnd(b10) + rnd(b10 - rnd(b10));
                    float rb11 = rnd(b11) + rnd(b11 - rnd(b11));
                    float m0 = mrow[mt][0], m1 = mrow[mt][1];
                    atomicAdd(&redA[lcA],   ra00*m0 + ra10*m1);
                    atomicAdd(&redA[lcA+1], ra01*m0 + ra11*m1);
                    atomicAdd(&redA[lcB],   rb00*m0 + rb10*m1);
                    atomicAdd(&redA[lcB+1], rb01*m0 + rb11*m1);
                    atomicAdd(&redB[lcA],   ra00*ra00*m0 + ra10*ra10*m1);
                    atomicAdd(&redB[lcA+1], ra01*ra01*m0 + ra11*ra11*m1);
                    atomicAdd(&redB[lcB],   rb00*rb00*m0 + rb10*rb10*m1);
                    atomicAdd(&redB[lcB+1], rb01*rb01*m0 + rb11*rb11*m1);
                }
                stsm4(tile_addr(mt, ntp), pk(a00,a01), pk(a10,a11), pk(b00,b01), pk(b10,b11));
            }
        }
        __syncthreads();
        copy_out(Chi);
        if (EMODE == 0 && tid < 128) {
            int v = pool_s[tid];
            if (v > 0) atomicMax((int*)&redT[batch * 256 + colBase + tid], v);
        }
        if (EMODE == 1 && tid < 128) {
            atomicAdd(&g_sum2[colBase + tid], redA[tid]);
            atomicAdd(&g_ss2[colBase + tid],  redB[tid]);
        }
        __syncthreads();
        // ---- pass 2: lo tile ----
#pragma unroll
        for (int mt = 0; mt < 2; mt++) {
#pragma unroll
            for (int ntp = 0; ntp < 4; ntp++) {
                int ntA = ntp * 2, ntB = ntA + 1;
                int lcA = warp_n*64 + ntA*8 + 2*t4;
                int lcB = warp_n*64 + ntB*8 + 2*t4;
                float bAx = bias_s[lcA], bAy = bias_s[lcA+1];
                float bBx = bias_s[lcB], bBy = bias_s[lcB+1];
                float a00 = acc[mt][ntA][0]+bAx, a01 = acc[mt][ntA][1]+bAy;
                float a10 = acc[mt][ntA][2]+bAx, a11 = acc[mt][ntA][3]+bAy;
                float b00 = acc[mt][ntB][0]+bBx, b01 = acc[mt][ntB][1]+bBy;
                float b10 = acc[mt][ntB][2]+bBx, b11 = acc[mt][ntB][3]+bBy;
                if (EMODE == 0) {
                    a00 *= mrow[mt][0]; a01 *= mrow[mt][0];
                    a10 *= mrow[mt][1]; a11 *= mrow[mt][1];
                    b00 *= mrow[mt][0]; b01 *= mrow[mt][0];
                    b10 *= mrow[mt][1]; b11 *= mrow[mt][1];
                }
                stsm4(tile_addr(mt, ntp),
                      pk(a00 - rnd(a00), a01 - rnd(a01)),
                      pk(a10 - rnd(a10), a11 - rnd(a11)),
                      pk(b00 - rnd(b00), b01 - rnd(b01)),
                      pk(b10 - rnd(b10), b11 - rnd(b11)));
            }
        }
        __syncthreads();
        copy_out(Clo);
    } else {
        // EMODE 2: masked max -> out
#pragma unroll
        for (int nt = 0; nt < 8; nt++) {
            int lc = warp_n * 64 + nt * 8 + 2 * t4;
            float bx = bias_s[lc], by = bias_s[lc + 1];
            float p0 = 0.f, p1 = 0.f;
#pragma unroll
            for (int mt = 0; mt < 2; mt++) {
                p0 = fmaxf(p0, (acc[mt][nt][0] + bx) * mrow[mt][0]);
                p1 = fmaxf(p1, (acc[mt][nt][1] + by) * mrow[mt][0]);
                p0 = fmaxf(p0, (acc[mt][nt][2] + bx) * mrow[mt][1]);
                p1 = fmaxf(p1, (acc[mt][nt][3] + by) * mrow[mt][1]);
            }
            if (p0 > 0.f) atomicMax(&pool_s[lc],     __float_as_int(p0));
            if (p1 > 0.f) atomicMax(&pool_s[lc + 1], __float_as_int(p1));
        }
        __syncthreads();
        if (tid < 128) {
            int v = pool_s[tid];
            if (v > 0) atomicMax((int*)&redT[batch * 128 + tid], v);
        }
    }
}

// ---------------- launch ----------------
extern "C" void kernel_launch(void* const* d_in, const int* in_sizes, int n_in,
                              void* d_out, int out_size) {
    const float* x   = (const float*)d_in[0];
    const int*   mask= (const int*)  d_in[1];
    const float* W1  = (const float*)d_in[2];
    const float* b1  = (const float*)d_in[3];
    const float* g1  = (const float*)d_in[4];
    const float* be1 = (const float*)d_in[5];
    const float* W2  = (const float*)d_in[6];
    const float* b2  = (const float*)d_in[7];
    const float* W3  = (const float*)d_in[8];
    const float* b3  = (const float*)d_in[9];
    const float* g2  = (const float*)d_in[10];
    const float* be2 = (const float*)d_in[11];
    const float* W4  = (const float*)d_in[12];
    const float* b4  = (const float*)d_in[13];
    float* out = (float*)d_out;

    float *p_pooled, *p_pb, *p_sc1, *p_sh1, *p_sc2, *p_sh2;
    __nv_bfloat16 *p_yhi, *p_ylo, *p_h2hi, *p_h2lo;
    __nv_bfloat16 *p_w2hi, *p_w2lo, *p_w3hi, *p_w3lo, *p_w4hi, *p_w4lo;
    cudaGetSymbolAddress((void**)&p_pooled, g_pooled);
    cudaGetSymbolAddress((void**)&p_pb,     g_pb);
    cudaGetSymbolAddress((void**)&p_sc1,    g_scale1);
    cudaGetSymbolAddress((void**)&p_sh1,    g_shift1);
    cudaGetSymbolAddress((void**)&p_sc2,    g_scale2);
    cudaGetSymbolAddress((void**)&p_sh2,    g_shift2);
    cudaGetSymbolAddress((void**)&p_yhi,    g_yhi);
    cudaGetSymbolAddress((void**)&p_ylo,    g_ylo);
    cudaGetSymbolAddress((void**)&p_h2hi,   g_h2hi);
    cudaGetSymbolAddress((void**)&p_h2lo,   g_h2lo);
    cudaGetSymbolAddress((void**)&p_w2hi,   g_w2hi);
    cudaGetSymbolAddress((void**)&p_w2lo,   g_w2lo);
    cudaGetSymbolAddress((void**)&p_w3hi,   g_w3hi);
    cudaGetSymbolAddress((void**)&p_w3lo,   g_w3lo);
    cudaGetSymbolAddress((void**)&p_w4hi,   g_w4hi);
    cudaGetSymbolAddress((void**)&p_w4lo,   g_w4lo);

    const int FBYTES = (128*3 + 256*2 + 768 + 128) * 4;
    const int SM_G2 = 8  * ABUF + FBYTES;
    const int SM_G3 = 10 * ABUF + FBYTES;
    const int SM_G4 = 8  * ABUF + FBYTES;
    cudaFuncSetAttribute(k_tc<128,2,0>, cudaFuncAttributeMaxDynamicSharedMemorySize, SM_G2);
    cudaFuncSetAttribute(k_tc<256,0,1>, cudaFuncAttributeMaxDynamicSharedMemorySize, SM_G3);
    cudaFuncSetAttribute(k_tc<256,1,2>, cudaFuncAttributeMaxDynamicSharedMemorySize, SM_G4);

    k_prep   <<<512, 256>>>(out, p_pooled, W2, W3, W4);
    k_h_stats<<<2048, 128>>>(x, mask, W1, b1);
    k_fin1   <<<1, 128>>>(g1, be1);

    // GEMM2: y = (relu(bn1(x@W1+b1)) @ W2 + b2)*mask [+ max-pool]
    k_tc<128,2,0><<<dim3(2, 2048), 256, SM_G2>>>(x, nullptr, nullptr, p_w2hi, p_w2lo,
        b2, mask, p_sc1, p_sh1, W1, b1, p_yhi, p_ylo, p_pooled);
    k_pb     <<<512, 256>>>(W3, b3);
    // GEMM3: h2 = y @ W3[:256] + pb[batch]  [+ fused BN2 stats], h2 stored split bf16
    k_tc<256,0,1><<<dim3(2, 2048), 256, SM_G3>>>(nullptr, p_yhi, p_ylo, p_w3hi, p_w3lo,
        p_pb, mask, nullptr, nullptr, nullptr, nullptr, p_h2hi, p_h2lo, nullptr);
    k_fin2   <<<1, 256>>>(g2, be2);
    // GEMM4: out = max_n ((relu(bn2(h2)) @ W4 + b4)*mask)
    k_tc<256,1,2><<<dim3(1, 2048), 256, SM_G4>>>(nullptr, p_h2hi, p_h2lo, p_w4hi, p_w4lo,
        b4, mask, p_sc2, p_sh2, nullptr, nullptr, nullptr, nullptr, out);
}